// round 8
// baseline (speedup 1.0000x reference)
#include <cuda_runtime.h>
#include <cstdint>

#define B_ 4
#define L_ 512
#define D_ 256
#define U_ 64
#define TI 8
#define TJ 32
#define NTROW (L_/TI)   // 64 row tiles per batch

// scratch for projections (allowed: __device__ globals, no allocation)
__device__ float g_q[B_*L_*U_];
__device__ float g_k[B_*L_*U_];

__device__ __forceinline__ float tanh_ap(float x){ float y; asm("tanh.approx.f32 %0, %1;" : "=f"(y) : "f"(x)); return y; }
__device__ __forceinline__ float ex2_ap(float x){ float y; asm("ex2.approx.f32 %0, %1;" : "=f"(y) : "f"(x)); return y; }
__device__ __forceinline__ unsigned long long dup2(float x){
    unsigned long long r; asm("mov.b64 %0, {%1, %1};" : "=l"(r) : "f"(x)); return r;
}
__device__ __forceinline__ void fma2(unsigned long long &a, unsigned long long x, unsigned long long y){
    asm("fma.rn.f32x2 %0, %1, %2, %0;" : "+l"(a) : "l"(x), "l"(y));
}
__device__ __forceinline__ void mul2(unsigned long long &a, unsigned long long x){
    asm("mul.rn.f32x2 %0, %0, %1;" : "+l"(a) : "l"(x));
}
__device__ __forceinline__ float2 unpack2(unsigned long long v){
    float lo, hi; asm("mov.b64 {%0, %1}, %2;" : "=f"(lo), "=f"(hi) : "l"(v)); return make_float2(lo, hi);
}
__device__ __forceinline__ unsigned smem_u32(const void* p){
    return (unsigned)__cvta_generic_to_shared(p);
}
__device__ __forceinline__ void cp16(unsigned dst, const void* src){
    asm volatile("cp.async.cg.shared.global [%0], [%1], 16;" :: "r"(dst), "l"(src));
}
__device__ __forceinline__ void cp_commit(){ asm volatile("cp.async.commit_group;"); }
__device__ __forceinline__ void cp_wait0(){ asm volatile("cp.async.wait_group 0;"); }
__device__ __forceinline__ void barg(int id){ asm volatile("bar.sync %0, 256;" :: "r"(id) : "memory"); }

// ---------------------------------------------------------------------------
// Phase 1: q = X@Wt ; k = X@Wx + bh   (packed f32x2 over u-pairs)
// 256 blocks x 128 threads. Each block: 16 rows (2 rows/thread).
// ---------------------------------------------------------------------------
__global__ void __launch_bounds__(128) proj_kernel(
    const float* __restrict__ X, const float* __restrict__ Wt,
    const float* __restrict__ Wx, const float* __restrict__ bh)
{
    __shared__ __align__(16) float W_s[128*U_];   // 32KB (half of W)
    __shared__ __align__(16) float x_s[16*D_];    // 16KB

    const int bid = blockIdx.x;
    const bool is_k = bid >= (B_*L_/16);
    const int rb = is_k ? bid - (B_*L_/16) : bid;
    const float* __restrict__ W = is_k ? Wx : Wt;
    const int t = threadIdx.x;
    const int row0 = rb * 16;

    for (int i = t; i < 16*D_; i += 128)
        x_s[i] = X[row0*D_ + i];

    const int quad = t & 15;
    const int r    = t >> 4;
    const float* xr0 = x_s + r*D_;
    const float* xr1 = x_s + (r+8)*D_;

    unsigned long long a01_0 = 0ull, a23_0 = 0ull;
    unsigned long long a01_1 = 0ull, a23_1 = 0ull;

    #pragma unroll
    for (int half = 0; half < 2; ++half) {
        __syncthreads();
        for (int i = t; i < 128*U_; i += 128) W_s[i] = W[half*128*U_ + i];
        __syncthreads();
        const float* x0 = xr0 + half*128;
        const float* x1 = xr1 + half*128;
        #pragma unroll 4
        for (int d = 0; d < 128; ++d) {
            ulonglong2 w2 = *reinterpret_cast<const ulonglong2*>(W_s + d*U_ + quad*4);
            unsigned long long xx0 = dup2(x0[d]);
            unsigned long long xx1 = dup2(x1[d]);
            fma2(a01_0, xx0, w2.x);
            fma2(a23_0, xx0, w2.y);
            fma2(a01_1, xx1, w2.x);
            fma2(a23_1, xx1, w2.y);
        }
    }

    float bx = 0.f, by = 0.f, bz = 0.f, bw = 0.f;
    if (is_k) { bx = bh[quad*4+0]; by = bh[quad*4+1]; bz = bh[quad*4+2]; bw = bh[quad*4+3]; }

    float* base = (is_k ? g_k : g_q);
    {
        float2 v01 = unpack2(a01_0), v23 = unpack2(a23_0);
        float4 o; o.x = v01.x+bx; o.y = v01.y+by; o.z = v23.x+bz; o.w = v23.y+bw;
        *reinterpret_cast<float4*>(base + (row0 + r)*U_ + quad*4) = o;
    }
    {
        float2 v01 = unpack2(a01_1), v23 = unpack2(a23_1);
        float4 o; o.x = v01.x+bx; o.y = v01.y+by; o.z = v23.x+bz; o.w = v23.y+bw;
        *reinterpret_cast<float4*>(base + (row0 + r + 8)*U_ + quad*4) = o;
    }
}

// ---------------------------------------------------------------------------
// Phase 2: R7 structure with the two pass-tiles run CONCURRENTLY.
// 128 CTAs x 512 threads. Group g = t>>8 (256 threads / 8 warps) handles
// tile (g==0 ? pr : 63-pr); groups sync via named barriers (1+g) and own
// private k/X double buffers -> 16 live warps/SM (4/SMSP) hide latency.
// Per-group smem block (80KB): kbuf 2x512 float4 (16KB) | Xs 2x8192 f (64KB)
// Tail: q_q 2x128 float4, wa4 16 float4, p4 2x256 f, alpha 2x8, sinv 2x8.
// ---------------------------------------------------------------------------
#define GRP_B (16384 + 65536)

__global__ void __launch_bounds__(512, 1) attn_kernel(
    const float* __restrict__ X, const float* __restrict__ Wa,
    float* __restrict__ out)
{
    extern __shared__ __align__(16) unsigned char smem_raw[];

    const int t  = threadIdx.x;
    const int g  = t >> 8;           // group 0/1
    const int tl = t & 255;          // thread-in-group
    const int w  = t >> 5, lane = t & 31;
    const int wl = w & 7;            // warp-in-group
    const int b  = blockIdx.x >> 5;
    const int pr = blockIdx.x & 31;

    unsigned char* grp = smem_raw + g*GRP_B;
    float4* kbuf = reinterpret_cast<float4*>(grp);                 // 16KB (2 bufs)
    float*  Xs   = reinterpret_cast<float*>(grp + 16384);          // 64KB (2 bufs)
    unsigned char* tail = smem_raw + 2*GRP_B;
    float4* q_q   = reinterpret_cast<float4*>(tail) + g*128;       // per-group 2KB
    float4* wa4   = reinterpret_cast<float4*>(tail + 4096);        // shared 256B
    float*  p4    = reinterpret_cast<float*>(tail + 4096 + 256) + g*(TI*TJ);
    float*  alpha_s = reinterpret_cast<float*>(tail + 4096 + 256 + 2048) + g*TI;
    float*  sinv    = alpha_s + 2*TI - g*TI + g*TI;  // after both alpha blocks
    sinv = reinterpret_cast<float*>(tail + 4096 + 256 + 2048 + 64) + g*TI;

    const float* __restrict__ Xb = X   + b*L_*D_;
    const float* __restrict__ kb = g_k + b*L_*U_;
    const float* __restrict__ qb = g_q + b*L_*U_;

    const int it  = g ? (NTROW - 1 - pr) : pr;
    const int i0  = it * TI;
    const int ntj = (i0 + TI - 1)/TJ + 1;
    const int gi  = i0 + wl;
    const int bid_bar = 1 + g;

    if (t < U_) reinterpret_cast<float*>(wa4)[t] = Wa[t] * 1.4426950408889634f;
    // q for this group's 8 rows (tl < 128 loads one float4 each)
    if (tl < 128) {
        int i = tl >> 4, uq = tl & 15;
        q_q[uq*TI + i] = *reinterpret_cast<const float4*>(qb + (i0+i)*U_ + uq*4);
    }

    // cp.async fill targets (tile-invariant)
    const int kf_uq0 = tl & 15,         kf_j0 = tl >> 4;
    const int kf_uq1 = (tl+256) & 15,   kf_j1 = (tl+256) >> 4;
    const unsigned k_dst0 = smem_u32(kbuf) + (kf_uq0*TJ + kf_j0)*16;
    const unsigned k_dst1 = smem_u32(kbuf) + (kf_uq1*TJ + kf_j1)*16;
    const unsigned x_dst0 = smem_u32(Xs) + tl*16;
    const unsigned KBUF_B = 512*16;     // 8KB per buffer
    const unsigned XS_B   = 8192*4;     // 32KB per buffer

    const int dp  = tl & 127;
    const int ih  = tl >> 7;
    const int ib0 = ih * 4;

    // prologue: async-fill buffer 0 (k + X for j-tile 0)
    cp16(k_dst0, kb + kf_j0*U_ + kf_uq0*4);
    cp16(k_dst1, kb + kf_j1*U_ + kf_uq1*4);
    #pragma unroll
    for (int rep = 0; rep < 8; ++rep) {
        int idx = tl + rep*256;
        cp16(x_dst0 + rep*4096, Xb + (idx>>6)*D_ + (idx&63)*4);
    }
    cp_commit();

    __syncthreads();   // wa4 + q_q visible to everyone (once)

    float m_run = -1e30f, s_run = 0.f;
    unsigned long long acc[4] = {0ull, 0ull, 0ull, 0ull};

    for (int jt = 0; jt < ntj; ++jt) {
        const int j0 = jt * TJ;
        const int cur = jt & 1;

        cp_wait0();
        barg(bid_bar);     // group's fills visible; prev PV done with other buf

        if (jt + 1 < ntj) {
            const int nxt = (jt + 1) & 1;
            const int j0n = j0 + TJ;
            cp16(k_dst0 + nxt*KBUF_B, kb + (j0n + kf_j0)*U_ + kf_uq0*4);
            cp16(k_dst1 + nxt*KBUF_B, kb + (j0n + kf_j1)*U_ + kf_uq1*4);
            #pragma unroll
            for (int rep = 0; rep < 8; ++rep) {
                int idx = tl + rep*256;
                cp16(x_dst0 + nxt*XS_B + rep*4096, Xb + (j0n + (idx>>6))*D_ + (idx&63)*4);
            }
            cp_commit();
        }

        // ---- score: e[gi][j0+lane] in log2 domain ----
        const float4* kc = kbuf + cur*512;
        float e0 = 0.f, e1 = 0.f;
        #pragma unroll
        for (int uq = 0; uq < 16; ++uq) {
            float4 kv = kc[uq*TJ + lane];    // conflict-free
            float4 qv = q_q[uq*TI + wl];     // broadcast
            float4 wa = wa4[uq];             // broadcast
            e0 += wa.x * tanh_ap(qv.x + kv.x);
            e1 += wa.y * tanh_ap(qv.y + kv.y);
            e0 += wa.z * tanh_ap(qv.z + kv.z);
            e1 += wa.w * tanh_ap(qv.w + kv.w);
        }
        float e = e0 + e1;
        const int gj = j0 + lane;
        if (gj > gi) e = -1e30f;   // causal: exp2 underflows to exact 0

        // ---- online softmax (warp = one row) ----
        float mt = e;
        #pragma unroll
        for (int off = 16; off; off >>= 1)
            mt = fmaxf(mt, __shfl_xor_sync(0xffffffffu, mt, off));
        float m_new = fmaxf(m_run, mt);
        float p = ex2_ap(e - m_new);
        float st = p;
        #pragma unroll
        for (int off = 16; off; off >>= 1)
            st += __shfl_xor_sync(0xffffffffu, st, off);
        float alpha = ex2_ap(m_run - m_new);
        s_run = s_run * alpha + st;
        m_run = m_new;
        p4[wl*TJ + lane] = p;
        if (lane == 0) alpha_s[wl] = alpha;
        barg(bid_bar);

        // ---- PV update (packed f32x2 over d-pairs; p via LDS.128 + ALU dup) ----
        #pragma unroll
        for (int i = 0; i < 4; ++i)
            mul2(acc[i], dup2(alpha_s[ib0+i]));

        const unsigned long long* xcol =
            reinterpret_cast<const unsigned long long*>(Xs + cur*8192) + dp; // row stride 128
        #pragma unroll
        for (int jc = 0; jc < TJ/4; ++jc) {
            unsigned long long xv0 = xcol[(jc*4+0)*(D_/2)];
            unsigned long long xv1 = xcol[(jc*4+1)*(D_/2)];
            unsigned long long xv2 = xcol[(jc*4+2)*(D_/2)];
            unsigned long long xv3 = xcol[(jc*4+3)*(D_/2)];
            float4 pv[4];
            #pragma unroll
            for (int i = 0; i < 4; ++i)
                pv[i] = *reinterpret_cast<const float4*>(&p4[(ib0+i)*TJ + jc*4]); // broadcast
            #pragma unroll
            for (int i = 0; i < 4; ++i) {
                const float* pf = reinterpret_cast<const float*>(&pv[i]);
                fma2(acc[i], xv0, dup2(pf[0]));
                fma2(acc[i], xv1, dup2(pf[1]));
                fma2(acc[i], xv2, dup2(pf[2]));
                fma2(acc[i], xv3, dup2(pf[3]));
            }
        }
        barg(bid_bar);     // p4/alpha consumed before next overwrite
    }

    // ---- finalize ----
    if (lane == 0) sinv[wl] = 1.0f / s_run;
    barg(bid_bar);
    #pragma unroll
    for (int i = 0; i < 4; ++i) {
        float2 v = unpack2(acc[i]);
        float is = sinv[ib0 + i];
        float2 o = make_float2(v.x * is, v.y * is);
        *reinterpret_cast<float2*>(out + (b*L_ + i0 + ib0 + i)*D_ + dp*2) = o;
    }
}

// ---------------------------------------------------------------------------
extern "C" void kernel_launch(void* const* d_in, const int* in_sizes, int n_in,
                              void* d_out, int out_size)
{
    const float* X  = (const float*)d_in[0];
    const float* Wt = (const float*)d_in[1];
    const float* Wx = (const float*)d_in[2];
    const float* bh = (const float*)d_in[3];
    const float* Wa = (const float*)d_in[4];
    // d_in[5] = ba : constant shift inside softmax -> mathematically a no-op

    const int attn_smem = 2*GRP_B + 4096 + 256 + 2048 + 64 + 64;  // ~170.4KB
    cudaFuncSetAttribute(attn_kernel, cudaFuncAttributeMaxDynamicSharedMemorySize, attn_smem);

    proj_kernel<<<2*(B_*L_/16), 128>>>(X, Wt, Wx, bh);
    attn_kernel<<<B_*(NTROW/2), 512, attn_smem>>>(X, Wa, (float*)d_out);
}

// round 9
// speedup vs baseline: 1.0694x; 1.0694x over previous
#include <cuda_runtime.h>
#include <cstdint>

#define B_ 4
#define L_ 512
#define D_ 256
#define U_ 64
#define TI 8
#define TJ 32
#define NTROW (L_/TI)   // 64 row tiles per batch

// scratch for projections (allowed: __device__ globals, no allocation)
__device__ float g_q[B_*L_*U_];
__device__ float g_k[B_*L_*U_];

__device__ __forceinline__ float tanh_ap(float x){ float y; asm("tanh.approx.f32 %0, %1;" : "=f"(y) : "f"(x)); return y; }
__device__ __forceinline__ float ex2_ap(float x){ float y; asm("ex2.approx.f32 %0, %1;" : "=f"(y) : "f"(x)); return y; }
__device__ __forceinline__ unsigned long long dup2(float x){
    unsigned long long r; asm("mov.b64 %0, {%1, %1};" : "=l"(r) : "f"(x)); return r;
}
__device__ __forceinline__ void fma2(unsigned long long &a, unsigned long long x, unsigned long long y){
    asm("fma.rn.f32x2 %0, %1, %2, %0;" : "+l"(a) : "l"(x), "l"(y));
}
__device__ __forceinline__ void mul2(unsigned long long &a, unsigned long long x){
    asm("mul.rn.f32x2 %0, %0, %1;" : "+l"(a) : "l"(x));
}
__device__ __forceinline__ float2 unpack2(unsigned long long v){
    float lo, hi; asm("mov.b64 {%0, %1}, %2;" : "=f"(lo), "=f"(hi) : "l"(v)); return make_float2(lo, hi);
}
__device__ __forceinline__ unsigned smem_u32(const void* p){
    return (unsigned)__cvta_generic_to_shared(p);
}
__device__ __forceinline__ void cp16(unsigned dst, const void* src){
    asm volatile("cp.async.cg.shared.global [%0], [%1], 16;" :: "r"(dst), "l"(src));
}
__device__ __forceinline__ void cp_commit(){ asm volatile("cp.async.commit_group;"); }
__device__ __forceinline__ void cp_wait0(){ asm volatile("cp.async.wait_group 0;"); }
__device__ __forceinline__ void barg(int id){ asm volatile("bar.sync %0, 256;" :: "r"(id) : "memory"); }

// ---------------------------------------------------------------------------
// Phase 1: q = X@Wt ; k = X@Wx + bh   (packed f32x2 over u-pairs)
// 256 blocks x 128 threads. Each block: 16 rows (2 rows/thread).
// ---------------------------------------------------------------------------
__global__ void __launch_bounds__(128) proj_kernel(
    const float* __restrict__ X, const float* __restrict__ Wt,
    const float* __restrict__ Wx, const float* __restrict__ bh)
{
    __shared__ __align__(16) float W_s[128*U_];   // 32KB (half of W)
    __shared__ __align__(16) float x_s[16*D_];    // 16KB

    const int bid = blockIdx.x;
    const bool is_k = bid >= (B_*L_/16);
    const int rb = is_k ? bid - (B_*L_/16) : bid;
    const float* __restrict__ W = is_k ? Wx : Wt;
    const int t = threadIdx.x;
    const int row0 = rb * 16;

    for (int i = t; i < 16*D_; i += 128)
        x_s[i] = X[row0*D_ + i];

    const int quad = t & 15;
    const int r    = t >> 4;
    const float* xr0 = x_s + r*D_;
    const float* xr1 = x_s + (r+8)*D_;

    unsigned long long a01_0 = 0ull, a23_0 = 0ull;
    unsigned long long a01_1 = 0ull, a23_1 = 0ull;

    #pragma unroll
    for (int half = 0; half < 2; ++half) {
        __syncthreads();
        for (int i = t; i < 128*U_; i += 128) W_s[i] = W[half*128*U_ + i];
        __syncthreads();
        const float* x0 = xr0 + half*128;
        const float* x1 = xr1 + half*128;
        #pragma unroll 4
        for (int d = 0; d < 128; ++d) {
            ulonglong2 w2 = *reinterpret_cast<const ulonglong2*>(W_s + d*U_ + quad*4);
            unsigned long long xx0 = dup2(x0[d]);
            unsigned long long xx1 = dup2(x1[d]);
            fma2(a01_0, xx0, w2.x);
            fma2(a23_0, xx0, w2.y);
            fma2(a01_1, xx1, w2.x);
            fma2(a23_1, xx1, w2.y);
        }
    }

    float bx = 0.f, by = 0.f, bz = 0.f, bw = 0.f;
    if (is_k) { bx = bh[quad*4+0]; by = bh[quad*4+1]; bz = bh[quad*4+2]; bw = bh[quad*4+3]; }

    float* base = (is_k ? g_k : g_q);
    {
        float2 v01 = unpack2(a01_0), v23 = unpack2(a23_0);
        float4 o; o.x = v01.x+bx; o.y = v01.y+by; o.z = v23.x+bz; o.w = v23.y+bw;
        *reinterpret_cast<float4*>(base + (row0 + r)*U_ + quad*4) = o;
    }
    {
        float2 v01 = unpack2(a01_1), v23 = unpack2(a23_1);
        float4 o; o.x = v01.x+bx; o.y = v01.y+by; o.z = v23.x+bz; o.w = v23.y+bw;
        *reinterpret_cast<float4*>(base + (row0 + r + 8)*U_ + quad*4) = o;
    }
}

// ---------------------------------------------------------------------------
// Phase 2: split-KV balanced dual-group attention. 128 CTAs x 512 threads.
// CTA -> row-tile pair {A=pr, B=63-pr}. 17 j-tile jobs split 9/8:
//   group 0: all ntjA tiles of A (direct output) + first sB=9-ntjA tiles of B
//   group 1: remaining 8 tiles of B
// B rows merged flash-decoding style from the two partials at the end.
// Inner loop identical to R8 (cp.async double-buffered k+X, online softmax,
// packed f32x2 PV). Groups sync on named barriers 1/2 and own private bufs.
// ---------------------------------------------------------------------------
#define GRP_B (16384 + 65536)

__global__ void __launch_bounds__(512, 1) attn_kernel(
    const float* __restrict__ X, const float* __restrict__ Wa,
    float* __restrict__ out)
{
    extern __shared__ __align__(16) unsigned char smem_raw[];

    const int t    = threadIdx.x;
    const int g    = t >> 8;           // group 0/1
    const int tl   = t & 255;          // thread-in-group
    const int lane = t & 31;
    const int wl   = (t >> 5) & 7;     // warp-in-group
    const int b    = blockIdx.x >> 5;
    const int pr   = blockIdx.x & 31;

    const int i0A  = pr * TI;
    const int i0B  = (63 - pr) * TI;
    const int ntjA = pr/4 + 1;             // tiles for row-tile A (1..8)
    const int sB   = 9 - ntjA;             // group0's B tiles [0, sB)
    const int njobs = g ? 8 : 9;           // group1 does B tiles [sB, ntjB)

    unsigned char* grp = smem_raw + g*GRP_B;
    float4* kbuf = reinterpret_cast<float4*>(grp);                 // 2x8KB
    float*  Xs   = reinterpret_cast<float*>(grp + 16384);          // 2x32KB
    unsigned char* tail = smem_raw + 2*GRP_B;
    float4* q_all  = reinterpret_cast<float4*>(tail);              // [rt*128+uq*8+i] 4KB
    float4* wa4    = reinterpret_cast<float4*>(tail + 4096);       // 256B
    float*  p4     = reinterpret_cast<float*>(tail + 4352) + g*256;
    float*  alpha_s= reinterpret_cast<float*>(tail + 6400) + g*8;
    float*  sinv   = reinterpret_cast<float*>(tail + 6464) + g*8;
    float*  paccb  = reinterpret_cast<float*>(tail + 6528);        // [g][8][256] 16KB
    float*  pacc   = paccb + g*2048;
    float*  pmb    = reinterpret_cast<float*>(tail + 6528 + 16384);// [g][8]
    float*  psb    = pmb + 16;                                     // [g][8]
    float*  pm     = pmb + g*8;
    float*  ps     = psb + g*8;

    const float* __restrict__ Xb = X   + b*L_*D_;
    const float* __restrict__ kb = g_k + b*L_*U_;
    const float* __restrict__ qb = g_q + b*L_*U_;

    if (t < U_) reinterpret_cast<float*>(wa4)[t] = Wa[t] * 1.4426950408889634f;
    if (t < 256) {                         // q for both row-tiles (16 rows)
        int rt = t >> 7, idx = t & 127;
        int i = idx >> 4, uq = idx & 15;
        int gr = (rt ? i0B : i0A) + i;
        q_all[rt*128 + uq*8 + i] = *reinterpret_cast<const float4*>(qb + gr*U_ + uq*4);
    }

    // cp.async fill targets (tile-invariant)
    const int kf_uq0 = tl & 15,        kf_j0 = tl >> 4;
    const int kf_uq1 = (tl+256) & 15,  kf_j1 = (tl+256) >> 4;
    const unsigned k_dst0 = smem_u32(kbuf) + (kf_uq0*TJ + kf_j0)*16;
    const unsigned k_dst1 = smem_u32(kbuf) + (kf_uq1*TJ + kf_j1)*16;
    const unsigned x_dst0 = smem_u32(Xs) + tl*16;
    const unsigned KBUF_B = 512*16;    // 8KB per buffer
    const unsigned XS_B   = 8192*4;    // 32KB per buffer

    const int dp  = tl & 127;
    const int ih  = tl >> 7;
    const int ib0 = ih * 4;
    const int bid_bar = 1 + g;

    // prologue: prefetch job 0 into buffer 0
    {
        const int j0p = g ? sB*TJ : 0;
        cp16(k_dst0, kb + (j0p + kf_j0)*U_ + kf_uq0*4);
        cp16(k_dst1, kb + (j0p + kf_j1)*U_ + kf_uq1*4);
        #pragma unroll
        for (int rep = 0; rep < 8; ++rep) {
            int idx = tl + rep*256;
            cp16(x_dst0 + rep*4096, Xb + (j0p + (idx>>6))*D_ + (idx&63)*4);
        }
        cp_commit();
    }
    __syncthreads();   // wa4 + q_all visible

    float m_run = -1e30f, s_run = 0.f;
    unsigned long long acc[4] = {0ull, 0ull, 0ull, 0ull};

    for (int n = 0; n < njobs; ++n) {
        // decode current job -> (row-tile rt, j0)
        int rt, j0;
        if (g == 0) {
            if (n < ntjA) { rt = 0; j0 = n*TJ; }
            else          { rt = 1; j0 = (n - ntjA)*TJ; }
        } else            { rt = 1; j0 = (sB + n)*TJ; }
        const int cur = n & 1;

        cp_wait0();
        barg(bid_bar);   // fills visible; prev PV done with other buf

        if (n + 1 < njobs) {
            int j0n;
            if (g == 0) j0n = (n+1 < ntjA) ? (n+1)*TJ : (n+1-ntjA)*TJ;
            else        j0n = (sB + n + 1)*TJ;
            const int nxt = (n + 1) & 1;
            cp16(k_dst0 + nxt*KBUF_B, kb + (j0n + kf_j0)*U_ + kf_uq0*4);
            cp16(k_dst1 + nxt*KBUF_B, kb + (j0n + kf_j1)*U_ + kf_uq1*4);
            #pragma unroll
            for (int rep = 0; rep < 8; ++rep) {
                int idx = tl + rep*256;
                cp16(x_dst0 + nxt*XS_B + rep*4096, Xb + (j0n + (idx>>6))*D_ + (idx&63)*4);
            }
            cp_commit();
        }

        // ---- score: e[gi][j0+lane] in log2 domain ----
        const int gi = (rt ? i0B : i0A) + wl;
        const float4* kc = kbuf + cur*512;
        const float4* qr = q_all + rt*128;
        float e0 = 0.f, e1 = 0.f;
        #pragma unroll
        for (int uq = 0; uq < 16; ++uq) {
            float4 kv = kc[uq*TJ + lane];    // conflict-free
            float4 qv = qr[uq*8 + wl];       // broadcast
            float4 wa = wa4[uq];             // broadcast
            e0 += wa.x * tanh_ap(qv.x + kv.x);
            e1 += wa.y * tanh_ap(qv.y + kv.y);
            e0 += wa.z * tanh_ap(qv.z + kv.z);
            e1 += wa.w * tanh_ap(qv.w + kv.w);
        }
        float e = e0 + e1;
        if (j0 + lane > gi) e = -1e30f;   // causal: exp2 underflows to exact 0

        // ---- online softmax (warp = one row) ----
        float mt = e;
        #pragma unroll
        for (int off = 16; off; off >>= 1)
            mt = fmaxf(mt, __shfl_xor_sync(0xffffffffu, mt, off));
        float m_new = fmaxf(m_run, mt);
        float p = ex2_ap(e - m_new);
        float st = p;
        #pragma unroll
        for (int off = 16; off; off >>= 1)
            st += __shfl_xor_sync(0xffffffffu, st, off);
        float alpha = ex2_ap(m_run - m_new);
        s_run = s_run * alpha + st;
        m_run = m_new;

        const bool direct  = (g == 0) && (n + 1 == ntjA);
        const bool seg_end = direct || (n + 1 == njobs);
        p4[wl*TJ + lane] = p;
        if (lane == 0) {
            alpha_s[wl] = alpha;
            if (seg_end) {
                if (direct) sinv[wl] = 1.0f / s_run;
                else { pm[wl] = m_run; ps[wl] = s_run; }
            }
        }
        barg(bid_bar);

        // ---- PV update (packed f32x2 over d-pairs; p via LDS.128 + ALU dup) ----
        #pragma unroll
        for (int i = 0; i < 4; ++i)
            mul2(acc[i], dup2(alpha_s[ib0+i]));

        const unsigned long long* xcol =
            reinterpret_cast<const unsigned long long*>(Xs + cur*8192) + dp;
        #pragma unroll
        for (int jc = 0; jc < TJ/4; ++jc) {
            unsigned long long xv0 = xcol[(jc*4+0)*(D_/2)];
            unsigned long long xv1 = xcol[(jc*4+1)*(D_/2)];
            unsigned long long xv2 = xcol[(jc*4+2)*(D_/2)];
            unsigned long long xv3 = xcol[(jc*4+3)*(D_/2)];
            float4 pv[4];
            #pragma unroll
            for (int i = 0; i < 4; ++i)
                pv[i] = *reinterpret_cast<const float4*>(&p4[(ib0+i)*TJ + jc*4]); // broadcast
            #pragma unroll
            for (int i = 0; i < 4; ++i) {
                const float* pf = reinterpret_cast<const float*>(&pv[i]);
                fma2(acc[i], xv0, dup2(pf[0]));
                fma2(acc[i], xv1, dup2(pf[1]));
                fma2(acc[i], xv2, dup2(pf[2]));
                fma2(acc[i], xv3, dup2(pf[3]));
            }
        }

        if (seg_end) {
            if (direct) {
                // row-tile A complete: write output, reset state for B segment
                #pragma unroll
                for (int i = 0; i < 4; ++i) {
                    float2 v = unpack2(acc[i]);
                    float is = sinv[ib0 + i];
                    *reinterpret_cast<float2*>(out + (b*L_ + i0A + ib0 + i)*D_ + dp*2)
                        = make_float2(v.x*is, v.y*is);
                    acc[i] = 0ull;
                }
                m_run = -1e30f; s_run = 0.f;
            } else {
                // flush partial (unnormalized acc) for B merge
                #pragma unroll
                for (int i = 0; i < 4; ++i) {
                    float2 v = unpack2(acc[i]);
                    *reinterpret_cast<float2*>(&pacc[(ib0+i)*D_ + dp*2]) = v;
                }
            }
        }
        barg(bid_bar);   // p4/alpha consumed before next overwrite
    }

    // ---- merge the two B partials (flash-decoding combine) ----
    __syncthreads();
    {
        const int r  = t >> 6;   // 0..7
        const int dq = t & 63;   // d-quad
        float m0 = pmb[r],  m1 = pmb[8 + r];
        float s0 = psb[r],  s1 = psb[8 + r];
        float M  = fmaxf(m0, m1);
        float w0 = ex2_ap(m0 - M), w1 = ex2_ap(m1 - M);
        float dn = 1.0f / (w0*s0 + w1*s1);
        float4 a0 = *reinterpret_cast<float4*>(&paccb[r*D_ + dq*4]);
        float4 a1 = *reinterpret_cast<float4*>(&paccb[2048 + r*D_ + dq*4]);
        float4 o;
        o.x = (w0*a0.x + w1*a1.x)*dn;
        o.y = (w0*a0.y + w1*a1.y)*dn;
        o.z = (w0*a0.z + w1*a1.z)*dn;
        o.w = (w0*a0.w + w1*a1.w)*dn;
        *reinterpret_cast<float4*>(out + (b*L_ + i0B + r)*D_ + dq*4) = o;
    }
}

// ---------------------------------------------------------------------------
extern "C" void kernel_launch(void* const* d_in, const int* in_sizes, int n_in,
                              void* d_out, int out_size)
{
    const float* X  = (const float*)d_in[0];
    const float* Wt = (const float*)d_in[1];
    const float* Wx = (const float*)d_in[2];
    const float* bh = (const float*)d_in[3];
    const float* Wa = (const float*)d_in[4];
    // d_in[5] = ba : constant shift inside softmax -> mathematically a no-op

    const int attn_smem = 2*GRP_B + 23040;   // ~182.5KB
    cudaFuncSetAttribute(attn_kernel, cudaFuncAttributeMaxDynamicSharedMemorySize, attn_smem);

    proj_kernel<<<2*(B_*L_/16), 128>>>(X, Wt, Wx, bh);
    attn_kernel<<<B_*(NTROW/2), 512, attn_smem>>>(X, Wa, (float*)d_out);
}

// round 10
// speedup vs baseline: 1.0798x; 1.0097x over previous
#include <cuda_runtime.h>
#include <cstdint>

#define B_ 4
#define L_ 512
#define D_ 256
#define U_ 64
#define TI 8
#define TJ 32
#define NTROW (L_/TI)   // 64 row tiles per batch

// scratch for projections (allowed: __device__ globals, no allocation)
__device__ float g_q[B_*L_*U_];
__device__ float g_k[B_*L_*U_];

__device__ __forceinline__ float tanh_ap(float x){ float y; asm("tanh.approx.f32 %0, %1;" : "=f"(y) : "f"(x)); return y; }
__device__ __forceinline__ float ex2_ap(float x){ float y; asm("ex2.approx.f32 %0, %1;" : "=f"(y) : "f"(x)); return y; }
__device__ __forceinline__ unsigned long long dup2(float x){
    unsigned long long r; asm("mov.b64 %0, {%1, %1};" : "=l"(r) : "f"(x)); return r;
}
__device__ __forceinline__ unsigned long long pack2f(float a, float b){
    unsigned long long r; asm("mov.b64 %0, {%1, %2};" : "=l"(r) : "f"(a), "f"(b)); return r;
}
__device__ __forceinline__ void fma2(unsigned long long &a, unsigned long long x, unsigned long long y){
    asm("fma.rn.f32x2 %0, %1, %2, %0;" : "+l"(a) : "l"(x), "l"(y));
}
__device__ __forceinline__ void mul2(unsigned long long &a, unsigned long long x){
    asm("mul.rn.f32x2 %0, %0, %1;" : "+l"(a) : "l"(x));
}
__device__ __forceinline__ float2 unpack2(unsigned long long v){
    float lo, hi; asm("mov.b64 {%0, %1}, %2;" : "=f"(lo), "=f"(hi) : "l"(v)); return make_float2(lo, hi);
}
__device__ __forceinline__ unsigned smem_u32(const void* p){
    return (unsigned)__cvta_generic_to_shared(p);
}
__device__ __forceinline__ void cp16(unsigned dst, const void* src){
    asm volatile("cp.async.cg.shared.global [%0], [%1], 16;" :: "r"(dst), "l"(src));
}
__device__ __forceinline__ void cp_commit(){ asm volatile("cp.async.commit_group;"); }
__device__ __forceinline__ void cp_wait0(){ asm volatile("cp.async.wait_group 0;"); }
__device__ __forceinline__ void barg(int id){ asm volatile("bar.sync %0, 256;" :: "r"(id) : "memory"); }

// ---------------------------------------------------------------------------
// Phase 1: q = X@Wt ; k = X@Wx + bh.  128 blocks x 256 threads, 32 rows/block.
// Full W (64KB) staged ONCE in dynamic smem; x as float4. Packed f32x2 FMA.
// ---------------------------------------------------------------------------
__global__ void __launch_bounds__(256) proj_kernel(
    const float* __restrict__ X, const float* __restrict__ Wt,
    const float* __restrict__ Wx, const float* __restrict__ bh)
{
    extern __shared__ __align__(16) float psm[];
    float* W_s = psm;            // 16384 floats (64KB)
    float* x_s = psm + 16384;    // 8192 floats (32KB)

    const int bid  = blockIdx.x;
    const bool is_k = bid >= 64;
    const int rb   = bid & 63;
    const float* __restrict__ W = is_k ? Wx : Wt;
    const int t    = threadIdx.x;
    const int row0 = rb * 32;

    const float4* W4 = reinterpret_cast<const float4*>(W);
    const float4* X4 = reinterpret_cast<const float4*>(X) + row0*(D_/4);
    for (int i = t; i < (D_*U_)/4; i += 256) reinterpret_cast<float4*>(W_s)[i] = W4[i];
    for (int i = t; i < (32*D_)/4;  i += 256) reinterpret_cast<float4*>(x_s)[i] = X4[i];
    __syncthreads();

    const int quad = t & 15;     // u = quad*4 .. +3
    const int r    = t >> 4;     // rows r and r+16
    const float4* xa4 = reinterpret_cast<const float4*>(x_s) + r*(D_/4);
    const float4* xb4 = reinterpret_cast<const float4*>(x_s) + (r+16)*(D_/4);

    unsigned long long a01_0 = 0ull, a23_0 = 0ull;
    unsigned long long a01_1 = 0ull, a23_1 = 0ull;

    #pragma unroll 2
    for (int d4 = 0; d4 < D_/4; ++d4) {
        float4 xa = xa4[d4];
        float4 xb = xb4[d4];
        const float* xaf = reinterpret_cast<const float*>(&xa);
        const float* xbf = reinterpret_cast<const float*>(&xb);
        #pragma unroll
        for (int c = 0; c < 4; ++c) {
            ulonglong2 w2 = *reinterpret_cast<const ulonglong2*>(W_s + (d4*4+c)*U_ + quad*4);
            unsigned long long xx0 = dup2(xaf[c]);
            unsigned long long xx1 = dup2(xbf[c]);
            fma2(a01_0, xx0, w2.x);
            fma2(a23_0, xx0, w2.y);
            fma2(a01_1, xx1, w2.x);
            fma2(a23_1, xx1, w2.y);
        }
    }

    float bx = 0.f, by = 0.f, bz = 0.f, bw = 0.f;
    if (is_k) { bx = bh[quad*4+0]; by = bh[quad*4+1]; bz = bh[quad*4+2]; bw = bh[quad*4+3]; }

    float* base = (is_k ? g_k : g_q);
    {
        float2 v01 = unpack2(a01_0), v23 = unpack2(a23_0);
        float4 o; o.x = v01.x+bx; o.y = v01.y+by; o.z = v23.x+bz; o.w = v23.y+bw;
        *reinterpret_cast<float4*>(base + (row0 + r)*U_ + quad*4) = o;
    }
    {
        float2 v01 = unpack2(a01_1), v23 = unpack2(a23_1);
        float4 o; o.x = v01.x+bx; o.y = v01.y+by; o.z = v23.x+bz; o.w = v23.y+bw;
        *reinterpret_cast<float4*>(base + (row0 + r + 16)*U_ + quad*4) = o;
    }
}

// ---------------------------------------------------------------------------
// Phase 2: split-KV balanced dual-group attention (R9 skeleton).
// Changes vs R9: 2 barriers/tile (redundant 3rd removed); PV remapped to
// 4 d x 2 rows per thread (halves p-dup movs + p LDS).
// ---------------------------------------------------------------------------
#define GRP_B (16384 + 65536)

__global__ void __launch_bounds__(512, 1) attn_kernel(
    const float* __restrict__ X, const float* __restrict__ Wa,
    float* __restrict__ out)
{
    extern __shared__ __align__(16) unsigned char smem_raw[];

    const int t    = threadIdx.x;
    const int g    = t >> 8;           // group 0/1
    const int tl   = t & 255;          // thread-in-group
    const int lane = t & 31;
    const int wl   = (t >> 5) & 7;     // warp-in-group
    const int b    = blockIdx.x >> 5;
    const int pr   = blockIdx.x & 31;

    const int i0A  = pr * TI;
    const int i0B  = (63 - pr) * TI;
    const int ntjA = pr/4 + 1;             // tiles for row-tile A (1..8)
    const int sB   = 9 - ntjA;             // group0's B tiles [0, sB)
    const int njobs = g ? 8 : 9;

    unsigned char* grp = smem_raw + g*GRP_B;
    float4* kbuf = reinterpret_cast<float4*>(grp);                 // 2x8KB
    float*  Xs   = reinterpret_cast<float*>(grp + 16384);          // 2x32KB
    unsigned char* tail = smem_raw + 2*GRP_B;
    float4* q_all  = reinterpret_cast<float4*>(tail);              // [rt*128+uq*8+i] 4KB
    float4* wa4    = reinterpret_cast<float4*>(tail + 4096);       // 256B
    float*  p4     = reinterpret_cast<float*>(tail + 4352) + g*256;
    float*  alpha_s= reinterpret_cast<float*>(tail + 6400) + g*8;
    float*  sinv   = reinterpret_cast<float*>(tail + 6464) + g*8;
    float*  paccb  = reinterpret_cast<float*>(tail + 6528);        // [g][8][256] 16KB
    float*  pacc   = paccb + g*2048;
    float*  pmb    = reinterpret_cast<float*>(tail + 6528 + 16384);// [g][8]
    float*  psb    = pmb + 16;
    float*  pm     = pmb + g*8;
    float*  ps     = psb + g*8;

    const float* __restrict__ Xb = X   + b*L_*D_;
    const float* __restrict__ kb = g_k + b*L_*U_;
    const float* __restrict__ qb = g_q + b*L_*U_;

    if (t < U_) reinterpret_cast<float*>(wa4)[t] = Wa[t] * 1.4426950408889634f;
    if (t < 256) {                         // q for both row-tiles (16 rows)
        int rt = t >> 7, idx = t & 127;
        int i = idx >> 4, uq = idx & 15;
        int gr = (rt ? i0B : i0A) + i;
        q_all[rt*128 + uq*8 + i] = *reinterpret_cast<const float4*>(qb + gr*U_ + uq*4);
    }

    // cp.async fill targets (tile-invariant)
    const int kf_uq0 = tl & 15,        kf_j0 = tl >> 4;
    const int kf_uq1 = (tl+256) & 15,  kf_j1 = (tl+256) >> 4;
    const unsigned k_dst0 = smem_u32(kbuf) + (kf_uq0*TJ + kf_j0)*16;
    const unsigned k_dst1 = smem_u32(kbuf) + (kf_uq1*TJ + kf_j1)*16;
    const unsigned x_dst0 = smem_u32(Xs) + tl*16;
    const unsigned KBUF_B = 512*16;    // 8KB per buffer
    const unsigned XS_B   = 8192*4;    // 32KB per buffer

    const int dq = tl & 63;            // d-quad: d = dq*4 .. +3
    const int rp = tl >> 6;            // row pair: rows 2rp, 2rp+1
    const int lr0 = 2*rp, lr1 = 2*rp + 1;
    const int bid_bar = 1 + g;

    // prologue: prefetch job 0 into buffer 0
    {
        const int j0p = g ? sB*TJ : 0;
        cp16(k_dst0, kb + (j0p + kf_j0)*U_ + kf_uq0*4);
        cp16(k_dst1, kb + (j0p + kf_j1)*U_ + kf_uq1*4);
        #pragma unroll
        for (int rep = 0; rep < 8; ++rep) {
            int idx = tl + rep*256;
            cp16(x_dst0 + rep*4096, Xb + (j0p + (idx>>6))*D_ + (idx&63)*4);
        }
        cp_commit();
    }
    __syncthreads();   // wa4 + q_all visible

    float m_run = -1e30f, s_run = 0.f;
    unsigned long long a0l = 0ull, a0h = 0ull, a1l = 0ull, a1h = 0ull;

    for (int n = 0; n < njobs; ++n) {
        // decode current job -> (row-tile rt, j0)
        int rt, j0;
        if (g == 0) {
            if (n < ntjA) { rt = 0; j0 = n*TJ; }
            else          { rt = 1; j0 = (n - ntjA)*TJ; }
        } else            { rt = 1; j0 = (sB + n)*TJ; }
        const int cur = n & 1;

        cp_wait0();
        barg(bid_bar);   // fills visible; prev PV (readers of p4 + other buf) done

        if (n + 1 < njobs) {
            int j0n;
            if (g == 0) j0n = (n+1 < ntjA) ? (n+1)*TJ : (n+1-ntjA)*TJ;
            else        j0n = (sB + n + 1)*TJ;
            const int nxt = (n + 1) & 1;
            cp16(k_dst0 + nxt*KBUF_B, kb + (j0n + kf_j0)*U_ + kf_uq0*4);
            cp16(k_dst1 + nxt*KBUF_B, kb + (j0n + kf_j1)*U_ + kf_uq1*4);
            #pragma unroll
            for (int rep = 0; rep < 8; ++rep) {
                int idx = tl + rep*256;
                cp16(x_dst0 + nxt*XS_B + rep*4096, Xb + (j0n + (idx>>6))*D_ + (idx&63)*4);
            }
            cp_commit();
        }

        // ---- score: e[gi][j0+lane] in log2 domain ----
        const int gi = (rt ? i0B : i0A) + wl;
        const float4* kc = kbuf + cur*512;
        const float4* qr = q_all + rt*128;
        float e0 = 0.f, e1 = 0.f;
        #pragma unroll
        for (int uq = 0; uq < 16; ++uq) {
            float4 kv = kc[uq*TJ + lane];    // conflict-free
            float4 qv = qr[uq*8 + wl];       // broadcast
            float4 wa = wa4[uq];             // broadcast
            e0 += wa.x * tanh_ap(qv.x + kv.x);
            e1 += wa.y * tanh_ap(qv.y + kv.y);
            e0 += wa.z * tanh_ap(qv.z + kv.z);
            e1 += wa.w * tanh_ap(qv.w + kv.w);
        }
        float e = e0 + e1;
        if (j0 + lane > gi) e = -1e30f;   // causal: exp2 underflows to exact 0

        // ---- online softmax (warp = one row) ----
        float mt = e;
        #pragma unroll
        for (int off = 16; off; off >>= 1)
            mt = fmaxf(mt, __shfl_xor_sync(0xffffffffu, mt, off));
        float m_new = fmaxf(m_run, mt);
        float p = ex2_ap(e - m_new);
        float st = p;
        #pragma unroll
        for (int off = 16; off; off >>= 1)
            st += __shfl_xor_sync(0xffffffffu, st, off);
        float alpha = ex2_ap(m_run - m_new);
        s_run = s_run * alpha + st;
        m_run = m_new;

        const bool direct  = (g == 0) && (n + 1 == ntjA);
        const bool seg_end = direct || (n + 1 == njobs);
        p4[wl*TJ + lane] = p;
        if (lane == 0) {
            alpha_s[wl] = alpha;
            if (seg_end) {
                if (direct) sinv[wl] = 1.0f / s_run;
                else { pm[wl] = m_run; ps[wl] = s_run; }
            }
        }
        barg(bid_bar);

        // ---- PV update: 4 d x 2 rows per thread, packed f32x2 ----
        {
            unsigned long long al0 = dup2(alpha_s[lr0]);
            unsigned long long al1 = dup2(alpha_s[lr1]);
            mul2(a0l, al0); mul2(a0h, al0);
            mul2(a1l, al1); mul2(a1h, al1);
        }
        const float4* X4s = reinterpret_cast<const float4*>(Xs + cur*8192);
        const float4* p0r = reinterpret_cast<const float4*>(&p4[lr0*TJ]);
        const float4* p1r = reinterpret_cast<const float4*>(&p4[lr1*TJ]);
        #pragma unroll
        for (int jc = 0; jc < TJ/4; ++jc) {
            float4 x0 = X4s[(jc*4+0)*(D_/4) + dq];
            float4 x1 = X4s[(jc*4+1)*(D_/4) + dq];
            float4 x2 = X4s[(jc*4+2)*(D_/4) + dq];
            float4 x3 = X4s[(jc*4+3)*(D_/4) + dq];
            float4 pv0 = p0r[jc];   // broadcast LDS.128
            float4 pv1 = p1r[jc];   // broadcast LDS.128
            const float* pf0 = reinterpret_cast<const float*>(&pv0);
            const float* pf1 = reinterpret_cast<const float*>(&pv1);
            const float4* xs[4] = { &x0, &x1, &x2, &x3 };
            #pragma unroll
            for (int j = 0; j < 4; ++j) {
                unsigned long long xl = pack2f(xs[j]->x, xs[j]->y);
                unsigned long long xh = pack2f(xs[j]->z, xs[j]->w);
                unsigned long long d0 = dup2(pf0[j]);
                unsigned long long d1 = dup2(pf1[j]);
                fma2(a0l, xl, d0); fma2(a0h, xh, d0);
                fma2(a1l, xl, d1); fma2(a1h, xh, d1);
            }
        }

        if (seg_end) {
            if (direct) {
                const float is0 = sinv[lr0], is1 = sinv[lr1];
                float2 vl = unpack2(a0l), vh = unpack2(a0h);
                float4 o0; o0.x = vl.x*is0; o0.y = vl.y*is0; o0.z = vh.x*is0; o0.w = vh.y*is0;
                *reinterpret_cast<float4*>(out + (b*L_ + i0A + lr0)*D_ + dq*4) = o0;
                vl = unpack2(a1l); vh = unpack2(a1h);
                float4 o1; o1.x = vl.x*is1; o1.y = vl.y*is1; o1.z = vh.x*is1; o1.w = vh.y*is1;
                *reinterpret_cast<float4*>(out + (b*L_ + i0A + lr1)*D_ + dq*4) = o1;
                a0l = a0h = a1l = a1h = 0ull;
                m_run = -1e30f; s_run = 0.f;
            } else {
                float2 vl = unpack2(a0l), vh = unpack2(a0h);
                float4 f0; f0.x = vl.x; f0.y = vl.y; f0.z = vh.x; f0.w = vh.y;
                *reinterpret_cast<float4*>(&pacc[lr0*D_ + dq*4]) = f0;
                vl = unpack2(a1l); vh = unpack2(a1h);
                float4 f1; f1.x = vl.x; f1.y = vl.y; f1.z = vh.x; f1.w = vh.y;
                *reinterpret_cast<float4*>(&pacc[lr1*D_ + dq*4]) = f1;
            }
        }
        // no end-of-loop barrier: next iteration's top barg orders p4/buffer reuse
    }

    // ---- merge the two B partials (flash-decoding combine) ----
    __syncthreads();
    {
        const int r  = t >> 6;   // 0..7
        const int dqm = t & 63;
        float m0 = pmb[r],  m1 = pmb[8 + r];
        float s0 = psb[r],  s1 = psb[8 + r];
        float M  = fmaxf(m0, m1);
        float w0 = ex2_ap(m0 - M), w1 = ex2_ap(m1 - M);
        float dn = 1.0f / (w0*s0 + w1*s1);
        float4 c0 = *reinterpret_cast<float4*>(&paccb[r*D_ + dqm*4]);
        float4 c1 = *reinterpret_cast<float4*>(&paccb[2048 + r*D_ + dqm*4]);
        float4 o;
        o.x = (w0*c0.x + w1*c1.x)*dn;
        o.y = (w0*c0.y + w1*c1.y)*dn;
        o.z = (w0*c0.z + w1*c1.z)*dn;
        o.w = (w0*c0.w + w1*c1.w)*dn;
        *reinterpret_cast<float4*>(out + (b*L_ + i0B + r)*D_ + dqm*4) = o;
    }
}

// ---------------------------------------------------------------------------
extern "C" void kernel_launch(void* const* d_in, const int* in_sizes, int n_in,
                              void* d_out, int out_size)
{
    const float* X  = (const float*)d_in[0];
    const float* Wt = (const float*)d_in[1];
    const float* Wx = (const float*)d_in[2];
    const float* bh = (const float*)d_in[3];
    const float* Wa = (const float*)d_in[4];
    // d_in[5] = ba : constant shift inside softmax -> mathematically a no-op

    const int proj_smem = (16384 + 8192) * 4;       // 96KB
    const int attn_smem = 2*GRP_B + 23040;          // ~182.5KB
    cudaFuncSetAttribute(proj_kernel, cudaFuncAttributeMaxDynamicSharedMemorySize, proj_smem);
    cudaFuncSetAttribute(attn_kernel, cudaFuncAttributeMaxDynamicSharedMemorySize, attn_smem);

    proj_kernel<<<128, 256, proj_smem>>>(X, Wt, Wx, bh);
    attn_kernel<<<B_*(NTROW/2), 512, attn_smem>>>(X, Wa, (float*)d_out);
}